// round 4
// baseline (speedup 1.0000x reference)
#include <cuda_runtime.h>
#include <cuda_bf16.h>
#include <cstddef>

// Problem constants
#define BB   2
#define NN   1024
#define CC   1024
#define HH   16
#define DH   64
#define MROWS (BB*NN)          // 2048 token rows
#define OUT_ELEMS  (BB*NN*CC)                 // 2,097,152
#define ATTN_ELEMS (BB*NN*NN*HH)              // 33,554,432

// ---------------- scratch (static __device__, allocation-free) ----------------
__device__ float g_mha_q[MROWS * CC];          // Q  (2048 x 1024)
__device__ float g_mha_kv[MROWS * 2 * CC];     // KV (2048 x 2048): cols [0,1024)=K, [1024,2048)=V
__device__ float g_mha_o[MROWS * CC];          // attention output before projection
__device__ float g_mha_attn[ATTN_ELEMS];       // attn in [b,h,n,m] layout (pre-transpose)

// ---------------- GEMM: C[M,N] = A[M,K] @ B[N,K]^T + bias[N] ----------------
// 128x128 block tile, BK=8, 256 threads, 8x8 micro-tile, register prefetch.
__global__ __launch_bounds__(256) void mha_gemm_bt(
    const float* __restrict__ A, const float* __restrict__ B,
    const float* __restrict__ bias, float* __restrict__ C,
    int M, int N, int K)
{
    __shared__ float As[8][128];
    __shared__ float Bs[8][128];

    const int t  = threadIdx.x;
    const int bm = blockIdx.y * 128;
    const int bn = blockIdx.x * 128;
    const int tx = t & 15;          // micro-tile column group
    const int ty = t >> 4;          // micro-tile row group

    const int lr = t >> 1;          // 0..127 (tile row for loads)
    const int ls = (t & 1) * 4;     // k segment 0 or 4

    const float* Ap = A + (size_t)(bm + lr) * K + ls;
    const float* Bp = B + (size_t)(bn + lr) * K + ls;

    float acc[8][8];
    #pragma unroll
    for (int i = 0; i < 8; i++)
        #pragma unroll
        for (int j = 0; j < 8; j++) acc[i][j] = 0.0f;

    float4 a4 = *(const float4*)(Ap);
    float4 b4 = *(const float4*)(Bp);

    for (int k0 = 0; k0 < K; k0 += 8) {
        As[ls+0][lr] = a4.x; As[ls+1][lr] = a4.y; As[ls+2][lr] = a4.z; As[ls+3][lr] = a4.w;
        Bs[ls+0][lr] = b4.x; Bs[ls+1][lr] = b4.y; Bs[ls+2][lr] = b4.z; Bs[ls+3][lr] = b4.w;
        __syncthreads();

        float4 a4n = a4, b4n = b4;
        if (k0 + 8 < K) {
            a4n = *(const float4*)(Ap + k0 + 8);
            b4n = *(const float4*)(Bp + k0 + 8);
        }

        #pragma unroll
        for (int kk = 0; kk < 8; kk++) {
            float ra[8], rb[8];
            *(float4*)(ra)     = *(const float4*)&As[kk][ty*8];
            *(float4*)(ra + 4) = *(const float4*)&As[kk][ty*8 + 4];
            *(float4*)(rb)     = *(const float4*)&Bs[kk][tx*8];
            *(float4*)(rb + 4) = *(const float4*)&Bs[kk][tx*8 + 4];
            #pragma unroll
            for (int i = 0; i < 8; i++)
                #pragma unroll
                for (int j = 0; j < 8; j++)
                    acc[i][j] += ra[i] * rb[j];
        }
        __syncthreads();
        a4 = a4n; b4 = b4n;
    }

    float bz[8];
    #pragma unroll
    for (int j = 0; j < 8; j++) bz[j] = bias[bn + tx*8 + j];

    #pragma unroll
    for (int i = 0; i < 8; i++) {
        float* Cr = C + (size_t)(bm + ty*8 + i) * N + bn + tx*8;
        #pragma unroll
        for (int j = 0; j < 8; j++) Cr[j] = acc[i][j] + bz[j];
    }
}

// ---------------- Attention: per (b, h, 32-row n-tile) ----------------
// smem: Qs[32][65] | Ks[128][65] (reused for V) | Sb[32][1024]
#define AT_QS   (32 * 65)
#define AT_KS   (128 * 65)
#define AT_SB   (32 * 1024)
#define AT_SMEM ((AT_QS + AT_KS + AT_SB) * 4)   // 172,672 bytes

__global__ __launch_bounds__(256) void mha_attn_kernel(
    const float* __restrict__ gq, const float* __restrict__ gkv,
    float* __restrict__ go, float* __restrict__ gattn)
{
    extern __shared__ float sm[];
    float* Qs = sm;
    float* Ks = sm + AT_QS;
    float* Sb = Ks + AT_KS;

    const int t  = threadIdx.x;
    const int nt = blockIdx.x;      // 0..31 (n tile)
    const int h  = blockIdx.y;      // 0..15
    const int b  = blockIdx.z;      // 0..1
    const int n0 = nt * 32;
    const int tx = t & 15;
    const int ty = t >> 4;          // 0..15 -> rows ty and ty+16

    // ---- load Q tile (32 rows x 64 d) ----
    #pragma unroll
    for (int r = 0; r < 2; r++) {
        int li = r * 256 + t;                 // 0..511 float4 slots
        int n  = li >> 4;
        int dq = (li & 15) << 2;
        float4 v = *(const float4*)(gq + (size_t)(b*NN + n0 + n) * CC + h*DH + dq);
        float* p = Qs + n*65 + dq;
        p[0] = v.x; p[1] = v.y; p[2] = v.z; p[3] = v.w;
    }

    // ---- S = scale * Q K^T, m-tiles of 128 ----
    const float* kbase = gkv + (size_t)(b*NN) * (2*CC) + h*DH;
    for (int mt = 0; mt < 8; mt++) {
        const int m0 = mt * 128;
        __syncthreads();   // Ks free (also covers Qs readiness on first iter)
        #pragma unroll
        for (int r = 0; r < 8; r++) {
            int li = r * 256 + t;             // 0..2047: 128 m x 16 float4
            int m  = li >> 4;
            int dq = (li & 15) << 2;
            float4 v = *(const float4*)(kbase + (size_t)(m0 + m) * (2*CC) + dq);
            float* p = Ks + m*65 + dq;
            p[0] = v.x; p[1] = v.y; p[2] = v.z; p[3] = v.w;
        }
        __syncthreads();

        float acc0[8], acc1[8];
        #pragma unroll
        for (int j = 0; j < 8; j++) { acc0[j] = 0.0f; acc1[j] = 0.0f; }

        #pragma unroll 4
        for (int d = 0; d < 64; d++) {
            float q0 = Qs[ty*65 + d];
            float q1 = Qs[(ty+16)*65 + d];
            #pragma unroll
            for (int j = 0; j < 8; j++) {
                float kk = Ks[(tx + 16*j)*65 + d];
                acc0[j] += q0 * kk;
                acc1[j] += q1 * kk;
            }
        }
        #pragma unroll
        for (int j = 0; j < 8; j++) {
            Sb[ty*1024 + m0 + tx + 16*j]      = acc0[j] * 0.125f;
            Sb[(ty+16)*1024 + m0 + tx + 16*j] = acc1[j] * 0.125f;
        }
    }
    __syncthreads();

    // ---- softmax over m (each warp: 4 rows) ----
    {
        const int w = t >> 5, lane = t & 31;
        #pragma unroll
        for (int rr = 0; rr < 4; rr++) {
            float* row = Sb + (w*4 + rr) * 1024;
            float mx = -1e30f;
            for (int m = lane; m < 1024; m += 32) mx = fmaxf(mx, row[m]);
            #pragma unroll
            for (int o = 16; o; o >>= 1) mx = fmaxf(mx, __shfl_xor_sync(0xffffffffu, mx, o));
            float sum = 0.0f;
            for (int m = lane; m < 1024; m += 32) {
                float e = __expf(row[m] - mx);
                row[m] = e;
                sum += e;
            }
            #pragma unroll
            for (int o = 16; o; o >>= 1) sum += __shfl_xor_sync(0xffffffffu, sum, o);
            float inv = 1.0f / sum;
            for (int m = lane; m < 1024; m += 32) row[m] *= inv;
        }
    }
    __syncthreads();

    // ---- write attn scratch, fully coalesced ([b,h,n,m] layout) ----
    {
        float* dst = gattn + ((size_t)((b*HH + h)*NN + n0)) * NN;
        #pragma unroll
        for (int r = 0; r < 32; r++) {
            int li = r * 256 + t;              // 0..8191 float4 slots
            float4 v = *(const float4*)(Sb + li*4);
            *(float4*)(dst + li*4) = v;
        }
    }

    // ---- O = P @ V ----
    float oacc0[4], oacc1[4];
    #pragma unroll
    for (int j = 0; j < 4; j++) { oacc0[j] = 0.0f; oacc1[j] = 0.0f; }

    const float* vbase = gkv + (size_t)(b*NN) * (2*CC) + CC + h*DH;
    for (int mt = 0; mt < 8; mt++) {
        const int m0 = mt * 128;
        __syncthreads();   // Ks free
        #pragma unroll
        for (int r = 0; r < 8; r++) {
            int li = r * 256 + t;
            int m  = li >> 4;
            int dq = (li & 15) << 2;
            float4 v = *(const float4*)(vbase + (size_t)(m0 + m) * (2*CC) + dq);
            float* p = Ks + m*65 + dq;
            p[0] = v.x; p[1] = v.y; p[2] = v.z; p[3] = v.w;
        }
        __syncthreads();

        #pragma unroll 4
        for (int mm = 0; mm < 128; mm++) {
            float p0 = Sb[ty*1024 + m0 + mm];
            float p1 = Sb[(ty+16)*1024 + m0 + mm];
            #pragma unroll
            for (int j = 0; j < 4; j++) {
                float vv = Ks[mm*65 + tx + 16*j];
                oacc0[j] += p0 * vv;
                oacc1[j] += p1 * vv;
            }
        }
    }
    {
        float* o0 = go + (size_t)(b*NN + n0 + ty)      * CC + h*DH;
        float* o1 = go + (size_t)(b*NN + n0 + ty + 16) * CC + h*DH;
        #pragma unroll
        for (int j = 0; j < 4; j++) {
            o0[tx + 16*j] = oacc0[j];
            o1[tx + 16*j] = oacc1[j];
        }
    }
}

// ---------------- transpose attn: [b,h,n,m] -> [b,n,m,h] ----------------
__global__ __launch_bounds__(256) void mha_transpose_attn(
    const float* __restrict__ src, float* __restrict__ dst)
{
    __shared__ float tile[16][257];
    const int t  = threadIdx.x;
    const int mc = blockIdx.x;   // 0..3 (m chunk of 256)
    const int n  = blockIdx.y;   // 0..1023
    const int b  = blockIdx.z;   // 0..1
    const int m0 = mc * 256;

    #pragma unroll
    for (int r = 0; r < 4; r++) {
        int li = r * 256 + t;             // 0..1023 float4 slots: 16 h x 64 f4
        int hh = li >> 6;
        int mq = (li & 63) << 2;
        float4 v = *(const float4*)(src + ((size_t)((b*HH + hh)*NN + n)) * NN + m0 + mq);
        tile[hh][mq]   = v.x;
        tile[hh][mq+1] = v.y;
        tile[hh][mq+2] = v.z;
        tile[hh][mq+3] = v.w;
    }
    __syncthreads();

    float* dbase = dst + ((size_t)(b*NN + n) * NN + m0) * HH;
    #pragma unroll
    for (int r = 0; r < 4; r++) {
        int li = r * 256 + t;             // 0..1023: 256 m x 4 h-quads
        int m  = li >> 2;
        int hq = (li & 3) << 2;
        float4 v;
        v.x = tile[hq+0][m];
        v.y = tile[hq+1][m];
        v.z = tile[hq+2][m];
        v.w = tile[hq+3][m];
        *(float4*)(dbase + (size_t)m * HH + hq) = v;
    }
}

// ---------------- launch ----------------
extern "C" void kernel_launch(void* const* d_in, const int* in_sizes, int n_in,
                              void* d_out, int out_size)
{
    const float* x   = (const float*)d_in[0];
    const float* Wq  = (const float*)d_in[1];
    const float* bq  = (const float*)d_in[2];
    const float* Wkv = (const float*)d_in[3];
    const float* bkv = (const float*)d_in[4];
    const float* Wp  = (const float*)d_in[5];
    const float* bp  = (const float*)d_in[6];

    float* out      = (float*)d_out;
    float* attn_out = out + (size_t)OUT_ELEMS;

    float* q    = nullptr;
    float* kv   = nullptr;
    float* o    = nullptr;
    float* attn = nullptr;
    cudaGetSymbolAddress((void**)&q,    g_mha_q);
    cudaGetSymbolAddress((void**)&kv,   g_mha_kv);
    cudaGetSymbolAddress((void**)&o,    g_mha_o);
    cudaGetSymbolAddress((void**)&attn, g_mha_attn);

    cudaFuncSetAttribute(mha_attn_kernel,
                         cudaFuncAttributeMaxDynamicSharedMemorySize, AT_SMEM);

    // Q = x @ Wq^T + bq       (2048 x 1024)
    mha_gemm_bt<<<dim3(CC/128, MROWS/128), 256>>>(x, Wq, bq, q, MROWS, CC, CC);
    // KV = x @ Wkv^T + bkv    (2048 x 2048)
    mha_gemm_bt<<<dim3(2*CC/128, MROWS/128), 256>>>(x, Wkv, bkv, kv, MROWS, 2*CC, CC);
    // attention (softmax'd attn to scratch, O to g_mha_o)
    mha_attn_kernel<<<dim3(NN/32, HH, BB), 256, AT_SMEM>>>(q, kv, o, attn);
    // out = O @ Wp^T + bp
    mha_gemm_bt<<<dim3(CC/128, MROWS/128), 256>>>(o, Wp, bp, out, MROWS, CC, CC);
    // attn -> [b,n,m,h] into d_out tail
    if (out_size >= (int)(OUT_ELEMS + ATTN_ELEMS)) {
        mha_transpose_attn<<<dim3(NN/256, NN, BB), 256>>>(attn, attn_out);
    }
}

// round 6
// speedup vs baseline: 2.0518x; 2.0518x over previous
#include <cuda_runtime.h>
#include <cuda_bf16.h>
#include <cstdint>
#include <cstddef>

// Problem constants
#define BB   2
#define NN   1024
#define CC   1024
#define HH   16
#define DH   64
#define MROWS (BB*NN)
#define OUT_ELEMS  (BB*NN*CC)                 // 2,097,152
#define ATTN_ELEMS (BB*NN*NN*HH)              // 33,554,432

// ---------------- scratch ----------------
__device__ float g_mha_q[MROWS * CC];
__device__ float g_mha_kv[MROWS * 2 * CC];
__device__ float g_mha_o[MROWS * CC];
__device__ float g_mha_attn[ATTN_ELEMS];      // [b,h,n,m]

// ---------------- tf32 helpers ----------------
__device__ __forceinline__ uint32_t f2tf(float x) {
    uint32_t r;
    asm("cvt.rna.tf32.f32 %0, %1;" : "=r"(r) : "f"(x));
    return r;
}

#define MMA_TF32(d, a, b) \
    asm volatile("mma.sync.aligned.m16n8k8.row.col.f32.tf32.tf32.f32 " \
        "{%0,%1,%2,%3}, {%4,%5,%6,%7}, {%8,%9}, {%0,%1,%2,%3};" \
        : "+f"((d)[0]), "+f"((d)[1]), "+f"((d)[2]), "+f"((d)[3]) \
        : "r"((a)[0]), "r"((a)[1]), "r"((a)[2]), "r"((a)[3]), \
          "r"((b)[0]), "r"((b)[1]))

// ================= GEMM: C[M,N] = A[M,K] @ B[N,K]^T + bias =================
// 128x128 block, 4 warps (2x2), warp tile 64x64, k-tile 16, tf32 mma.
#define GSTR 20   // smem stride in words (16 + 4 pad): conflict-free frag loads

__global__ __launch_bounds__(128, 2) void mha_gemm_tc(
    const float* __restrict__ A, const float* __restrict__ B,
    const float* __restrict__ bias, float* __restrict__ C,
    int M, int N, int K)
{
    __shared__ uint32_t As[128 * GSTR];
    __shared__ uint32_t Bs[128 * GSTR];

    const int t    = threadIdx.x;
    const int lane = t & 31;
    const int w    = t >> 5;
    const int bm   = blockIdx.y * 128;
    const int bn   = blockIdx.x * 128;
    const int wm   = (w >> 1) * 64;
    const int wn   = (w & 1) * 64;
    const int g    = lane >> 2;       // group id 0..7
    const int tg   = lane & 3;        // thread-in-group 0..3

    float acc[4][8][4];
    #pragma unroll
    for (int mi = 0; mi < 4; mi++)
        #pragma unroll
        for (int ni = 0; ni < 8; ni++)
            #pragma unroll
            for (int r = 0; r < 4; r++) acc[mi][ni][r] = 0.0f;

    const float* Ap = A + (size_t)(bm + t) * K;
    const float* Bp = B + (size_t)(bn + t) * K;

    float4 la[4], lb[4];
    #pragma unroll
    for (int q = 0; q < 4; q++) {
        la[q] = *(const float4*)(Ap + q * 4);
        lb[q] = *(const float4*)(Bp + q * 4);
    }

    for (int k0 = 0; k0 < K; k0 += 16) {
        // store current tile (cvt to tf32)
        #pragma unroll
        for (int q = 0; q < 4; q++) {
            uint4 sa, sb;
            sa.x = f2tf(la[q].x); sa.y = f2tf(la[q].y); sa.z = f2tf(la[q].z); sa.w = f2tf(la[q].w);
            sb.x = f2tf(lb[q].x); sb.y = f2tf(lb[q].y); sb.z = f2tf(lb[q].z); sb.w = f2tf(lb[q].w);
            *(uint4*)&As[t * GSTR + q * 4] = sa;
            *(uint4*)&Bs[t * GSTR + q * 4] = sb;
        }
        __syncthreads();

        if (k0 + 16 < K) {
            #pragma unroll
            for (int q = 0; q < 4; q++) {
                la[q] = *(const float4*)(Ap + k0 + 16 + q * 4);
                lb[q] = *(const float4*)(Bp + k0 + 16 + q * 4);
            }
        }

        #pragma unroll
        for (int kk = 0; kk < 16; kk += 8) {
            uint32_t af[4][4], bf[8][2];
            #pragma unroll
            for (int mi = 0; mi < 4; mi++) {
                int r = wm + mi * 16 + g;
                int c = kk + tg;
                af[mi][0] = As[r * GSTR + c];
                af[mi][1] = As[(r + 8) * GSTR + c];
                af[mi][2] = As[r * GSTR + c + 4];
                af[mi][3] = As[(r + 8) * GSTR + c + 4];
            }
            #pragma unroll
            for (int ni = 0; ni < 8; ni++) {
                int r = wn + ni * 8 + g;
                int c = kk + tg;
                bf[ni][0] = Bs[r * GSTR + c];
                bf[ni][1] = Bs[r * GSTR + c + 4];
            }
            #pragma unroll
            for (int mi = 0; mi < 4; mi++)
                #pragma unroll
                for (int ni = 0; ni < 8; ni++)
                    MMA_TF32(acc[mi][ni], af[mi], bf[ni]);
        }
        __syncthreads();
    }

    // epilogue
    #pragma unroll
    for (int mi = 0; mi < 4; mi++) {
        int r0 = bm + wm + mi * 16 + g;
        #pragma unroll
        for (int ni = 0; ni < 8; ni++) {
            int c0 = bn + wn + ni * 8 + 2 * tg;
            float bx = bias[c0], by = bias[c0 + 1];
            float2 v0 = make_float2(acc[mi][ni][0] + bx, acc[mi][ni][1] + by);
            float2 v1 = make_float2(acc[mi][ni][2] + bx, acc[mi][ni][3] + by);
            *(float2*)&C[(size_t)r0 * N + c0]       = v0;
            *(float2*)&C[(size_t)(r0 + 8) * N + c0] = v1;
        }
    }
}

// ================= Attention (tf32 mma) =================
// Per (b, h, 32-row n-tile). 256 threads = 8 warps.
// smem words: Qs 32*68 (tf32) | KVs 256*72 (tf32, K uses stride 68, V stride 72) | Sb 32*1044 (f32)
#define QSTR 68
#define KSTR 68
#define VSTR 72
#define SSTR 1044
#define AT_Q_WORDS  (32 * QSTR)
#define AT_KV_WORDS (256 * VSTR)
#define AT_S_WORDS  (32 * SSTR)
#define AT_SMEM ((AT_Q_WORDS + AT_KV_WORDS + AT_S_WORDS) * 4)   // 216,064 B

__global__ __launch_bounds__(256) void mha_attn_tc(
    const float* __restrict__ gq, const float* __restrict__ gkv,
    float* __restrict__ go, float* __restrict__ gattn)
{
    extern __shared__ uint32_t sm_u[];
    uint32_t* Qs  = sm_u;
    uint32_t* KVs = sm_u + AT_Q_WORDS;
    float*    Sb  = (float*)(sm_u + AT_Q_WORDS + AT_KV_WORDS);

    const int t    = threadIdx.x;
    const int lane = t & 31;
    const int w    = t >> 5;         // 0..7
    const int g    = lane >> 2;      // 0..7
    const int tg   = lane & 3;       // 0..3
    const int nt   = blockIdx.x;     // 0..31
    const int h    = blockIdx.y;     // 0..15
    const int b    = blockIdx.z;     // 0..1
    const int n0   = nt * 32;

    // ---- load Q tile (32 x 64), cvt to tf32 ----
    #pragma unroll
    for (int r = 0; r < 2; r++) {
        int li = r * 256 + t;            // 512 float4 slots
        int n  = li >> 4;
        int dq = (li & 15) << 2;
        float4 v = *(const float4*)(gq + (size_t)(b * NN + n0 + n) * CC + h * DH + dq);
        uint4 u;
        u.x = f2tf(v.x); u.y = f2tf(v.y); u.z = f2tf(v.z); u.w = f2tf(v.w);
        *(uint4*)&Qs[n * QSTR + dq] = u;
    }
    __syncthreads();

    // ---- preload Q fragments (warp's n-tile = w&1), register-resident ----
    uint32_t qa[8][4];
    {
        int r = (w & 1) * 16 + g;
        #pragma unroll
        for (int kd = 0; kd < 8; kd++) {
            int c = kd * 8 + tg;
            qa[kd][0] = Qs[r * QSTR + c];
            qa[kd][1] = Qs[(r + 8) * QSTR + c];
            qa[kd][2] = Qs[r * QSTR + c + 4];
            qa[kd][3] = Qs[(r + 8) * QSTR + c + 4];
        }
    }

    const float* kbase = gkv + (size_t)(b * NN) * (2 * CC) + h * DH;
    const float* vbase = kbase + CC;

    // ---- S = scale * Q K^T over 4 chunks of 256 m-rows ----
    for (int ch = 0; ch < 4; ch++) {
        const int m0 = ch * 256;
        __syncthreads();             // KVs free
        #pragma unroll
        for (int r = 0; r < 16; r++) {
            int li  = r * 256 + t;                // 4096 float4 slots: 256 rows x 16 quads
            int row = li >> 4;
            int dq  = (li & 15) << 2;
            float4 v = *(const float4*)(kbase + (size_t)(m0 + row) * (2 * CC) + dq);
            uint4 u;
            u.x = f2tf(v.x); u.y = f2tf(v.y); u.z = f2tf(v.z); u.w = f2tf(v.w);
            *(uint4*)&KVs[row * KSTR + dq] = u;
        }
        __syncthreads();

        float acc[8][4];
        #pragma unroll
        for (int mt = 0; mt < 8; mt++)
            #pragma unroll
            for (int r = 0; r < 4; r++) acc[mt][r] = 0.0f;

        #pragma unroll
        for (int kd = 0; kd < 8; kd++) {
            uint32_t bf[8][2];
            #pragma unroll
            for (int mt = 0; mt < 8; mt++) {
                int r = (w >> 1) * 64 + mt * 8 + g;
                int c = kd * 8 + tg;
                bf[mt][0] = KVs[r * KSTR + c];
                bf[mt][1] = KVs[r * KSTR + c + 4];
            }
            #pragma unroll
            for (int mt = 0; mt < 8; mt++)
                MMA_TF32(acc[mt], qa[kd], bf[mt]);
        }

        int row = (w & 1) * 16 + g;
        #pragma unroll
        for (int mt = 0; mt < 8; mt++) {
            int col = m0 + (w >> 1) * 64 + mt * 8 + 2 * tg;
            Sb[row * SSTR + col]           = acc[mt][0] * 0.125f;
            Sb[row * SSTR + col + 1]       = acc[mt][1] * 0.125f;
            Sb[(row + 8) * SSTR + col]     = acc[mt][2] * 0.125f;
            Sb[(row + 8) * SSTR + col + 1] = acc[mt][3] * 0.125f;
        }
    }
    __syncthreads();

    // ---- softmax over m (each warp: 4 rows) ----
    {
        #pragma unroll
        for (int rr = 0; rr < 4; rr++) {
            float* row = Sb + (w * 4 + rr) * SSTR;
            float mx = -1e30f;
            for (int m = lane; m < 1024; m += 32) mx = fmaxf(mx, row[m]);
            #pragma unroll
            for (int o = 16; o; o >>= 1) mx = fmaxf(mx, __shfl_xor_sync(0xffffffffu, mx, o));
            float sum = 0.0f;
            for (int m = lane; m < 1024; m += 32) {
                float e = __expf(row[m] - mx);
                row[m] = e;
                sum += e;
            }
            #pragma unroll
            for (int o = 16; o; o >>= 1) sum += __shfl_xor_sync(0xffffffffu, sum, o);
            float inv = 1.0f / sum;
            for (int m = lane; m < 1024; m += 32) row[m] *= inv;
        }
    }
    __syncthreads();

    // ---- write attn scratch ([b,h,n,m], coalesced) ----
    {
        float* dst = gattn + ((size_t)((b * HH + h) * NN + n0)) * NN;
        #pragma unroll
        for (int r = 0; r < 32; r++) {
            int li  = r * 256 + t;               // 8192 float4 slots
            int row = li >> 8;
            int mq  = (li & 255) << 2;
            float4 v = *(const float4*)(Sb + row * SSTR + mq);
            *(float4*)(dst + (size_t)row * NN + mq) = v;
        }
    }

    // ---- O = P @ V  (warp: n-tile = w&1 rows, d-group = w>>1, 2 n8 tiles) ----
    float oacc[2][4];
    #pragma unroll
    for (int dt = 0; dt < 2; dt++)
        #pragma unroll
        for (int r = 0; r < 4; r++) oacc[dt][r] = 0.0f;

    for (int ch = 0; ch < 4; ch++) {
        const int m0 = ch * 256;
        __syncthreads();             // KVs free
        #pragma unroll
        for (int r = 0; r < 16; r++) {
            int li  = r * 256 + t;
            int row = li >> 4;
            int dq  = (li & 15) << 2;
            float4 v = *(const float4*)(vbase + (size_t)(m0 + row) * (2 * CC) + dq);
            uint4 u;
            u.x = f2tf(v.x); u.y = f2tf(v.y); u.z = f2tf(v.z); u.w = f2tf(v.w);
            *(uint4*)&KVs[row * VSTR + dq] = u;
        }
        __syncthreads();

        int arow = (w & 1) * 16 + g;
        #pragma unroll 8
        for (int ks = 0; ks < 32; ks++) {
            int mk = m0 + ks * 8;
            uint32_t af[4];
            af[0] = f2tf(Sb[arow * SSTR + mk + tg]);
            af[1] = f2tf(Sb[(arow + 8) * SSTR + mk + tg]);
            af[2] = f2tf(Sb[arow * SSTR + mk + tg + 4]);
            af[3] = f2tf(Sb[(arow + 8) * SSTR + mk + tg + 4]);
            uint32_t bf[2][2];
            #pragma unroll
            for (int dt = 0; dt < 2; dt++) {
                int vr = ks * 8 + tg;
                int vc = (w >> 1) * 16 + dt * 8 + g;
                bf[dt][0] = KVs[vr * VSTR + vc];
                bf[dt][1] = KVs[(vr + 4) * VSTR + vc];
            }
            MMA_TF32(oacc[0], af, bf[0]);
            MMA_TF32(oacc[1], af, bf[1]);
        }
    }

    {
        int row = (w & 1) * 16 + g;
        float* o0 = go + (size_t)(b * NN + n0 + row) * CC + h * DH + (w >> 1) * 16;
        int col = 2 * tg;
        #pragma unroll
        for (int dt = 0; dt < 2; dt++) {
            *(float2*)&o0[dt * 8 + col]          = make_float2(oacc[dt][0], oacc[dt][1]);
            *(float2*)&o0[8 * CC + dt * 8 + col] = make_float2(oacc[dt][2], oacc[dt][3]);
        }
    }
}

// ---------------- transpose attn: [b,h,n,m] -> [b,n,m,h] ----------------
__global__ __launch_bounds__(256) void mha_transpose_attn(
    const float* __restrict__ src, float* __restrict__ dst)
{
    __shared__ float tile[16][257];
    const int t  = threadIdx.x;
    const int mc = blockIdx.x;   // 0..3
    const int n  = blockIdx.y;   // 0..1023
    const int b  = blockIdx.z;   // 0..1
    const int m0 = mc * 256;

    #pragma unroll
    for (int r = 0; r < 4; r++) {
        int li = r * 256 + t;             // 1024 f4 slots: 16 h x 64 f4
        int hh = li >> 6;
        int mq = (li & 63) << 2;
        float4 v = *(const float4*)(src + ((size_t)((b * HH + hh) * NN + n)) * NN + m0 + mq);
        tile[hh][mq]     = v.x;
        tile[hh][mq + 1] = v.y;
        tile[hh][mq + 2] = v.z;
        tile[hh][mq + 3] = v.w;
    }
    __syncthreads();

    float* dbase = dst + ((size_t)(b * NN + n) * NN + m0) * HH;
    #pragma unroll
    for (int r = 0; r < 4; r++) {
        int li = r * 256 + t;             // 1024: 256 m x 4 h-quads
        int m  = li >> 2;
        int hq = (li & 3) << 2;
        float4 v;
        v.x = tile[hq + 0][m];
        v.y = tile[hq + 1][m];
        v.z = tile[hq + 2][m];
        v.w = tile[hq + 3][m];
        *(float4*)(dbase + (size_t)m * HH + hq) = v;
    }
}

// ---------------- launch ----------------
extern "C" void kernel_launch(void* const* d_in, const int* in_sizes, int n_in,
                              void* d_out, int out_size)
{
    const float* x   = (const float*)d_in[0];
    const float* Wq  = (const float*)d_in[1];
    const float* bq  = (const float*)d_in[2];
    const float* Wkv = (const float*)d_in[3];
    const float* bkv = (const float*)d_in[4];
    const float* Wp  = (const float*)d_in[5];
    const float* bp  = (const float*)d_in[6];

    float* out      = (float*)d_out;
    float* attn_out = out + (size_t)OUT_ELEMS;

    float* q = nullptr; float* kv = nullptr; float* o = nullptr; float* attn = nullptr;
    cudaGetSymbolAddress((void**)&q,    g_mha_q);
    cudaGetSymbolAddress((void**)&kv,   g_mha_kv);
    cudaGetSymbolAddress((void**)&o,    g_mha_o);
    cudaGetSymbolAddress((void**)&attn, g_mha_attn);

    cudaFuncSetAttribute(mha_attn_tc,
                         cudaFuncAttributeMaxDynamicSharedMemorySize, AT_SMEM);

    // Q = x @ Wq^T + bq
    mha_gemm_tc<<<dim3(CC / 128, MROWS / 128), 128>>>(x, Wq, bq, q, MROWS, CC, CC);
    // KV = x @ Wkv^T + bkv
    mha_gemm_tc<<<dim3(2 * CC / 128, MROWS / 128), 128>>>(x, Wkv, bkv, kv, MROWS, 2 * CC, CC);
    // attention
    mha_attn_tc<<<dim3(NN / 32, HH, BB), 256, AT_SMEM>>>(q, kv, o, attn);
    // out = O @ Wp^T + bp
    mha_gemm_tc<<<dim3(CC / 128, MROWS / 128), 128>>>(o, Wp, bp, out, MROWS, CC, CC);
    // attn -> [b,n,m,h]
    if (out_size >= (int)(OUT_ELEMS + ATTN_ELEMS)) {
        mha_transpose_attn<<<dim3(NN / 256, NN, BB), 256>>>(attn, attn_out);
    }
}

// round 9
// speedup vs baseline: 2.3062x; 1.1240x over previous
#include <cuda_runtime.h>
#include <cuda_bf16.h>
#include <cstdint>
#include <cstddef>

// Problem constants
#define BB   2
#define NN   1024
#define CC   1024
#define HH   16
#define DH   64
#define MROWS (BB*NN)
#define OUT_ELEMS  (BB*NN*CC)                 // 2,097,152
#define ATTN_ELEMS (BB*NN*NN*HH)              // 33,554,432

// ---------------- scratch ----------------
__device__ float g_mha_q[MROWS * CC];
__device__ float g_mha_kv[MROWS * 2 * CC];
__device__ float g_mha_o[MROWS * CC];
__device__ float g_mha_attn[ATTN_ELEMS];      // [b,h,n,m]

// ---------------- tf32 helpers ----------------
__device__ __forceinline__ uint32_t f2tf(float x) {
    uint32_t r;
    asm("cvt.rna.tf32.f32 %0, %1;" : "=r"(r) : "f"(x));
    return r;
}

#define MMA_TF32(d, a, b) \
    asm volatile("mma.sync.aligned.m16n8k8.row.col.f32.tf32.tf32.f32 " \
        "{%0,%1,%2,%3}, {%4,%5,%6,%7}, {%8,%9}, {%0,%1,%2,%3};" \
        : "+f"((d)[0]), "+f"((d)[1]), "+f"((d)[2]), "+f"((d)[3]) \
        : "r"((a)[0]), "r"((a)[1]), "r"((a)[2]), "r"((a)[3]), \
          "r"((b)[0]), "r"((b)[1]))

// ================= GEMM: C = A @ B^T + bias, split-output variant =================
// 128x128 block, 256 threads (8 warps, 2m x 4n), warp tile 64x32, k-tile 16.
// Double-buffered smem, one __syncthreads per k-iter.
// Columns [0, 1024) -> C0 (weights B0, bias0, ldc 1024)
// Columns [1024, ...) -> C1 (weights B1, bias1, ldc 2048)
#define GSTR 20

__global__ __launch_bounds__(256) void mha_gemm8(
    const float* __restrict__ A,
    const float* __restrict__ B0, const float* __restrict__ B1,
    const float* __restrict__ bias0, const float* __restrict__ bias1,
    float* __restrict__ C0, float* __restrict__ C1, int K)
{
    __shared__ uint32_t As[2][128 * GSTR];
    __shared__ uint32_t Bs[2][128 * GSTR];

    const int t    = threadIdx.x;
    const int lane = t & 31;
    const int w    = t >> 5;         // 0..7
    const int bm   = blockIdx.y * 128;
    const int bn   = blockIdx.x * 128;
    const int wm   = (w >> 2) * 64;  // 0 or 64
    const int wn   = (w & 3) * 32;   // 0..96
    const int g    = lane >> 2;      // 0..7
    const int tg   = lane & 3;       // 0..3

    const int lr = t >> 1;           // 0..127 (tile row for loads)
    const int ls = (t & 1) * 8;      // k segment 0 or 8

    float acc[4][4][4];
    #pragma unroll
    for (int mi = 0; mi < 4; mi++)
        #pragma unroll
        for (int ni = 0; ni < 4; ni++)
            #pragma unroll
            for (int r = 0; r < 4; r++) acc[mi][ni][r] = 0.0f;

    const float* Ap = A + (size_t)(bm + lr) * K;
    const float* Bp;
    {
        int cn = bn + lr;
        Bp = (cn < CC) ? (B0 + (size_t)cn * K)
                       : (B1 + (size_t)(cn - CC) * K);
    }

    float4 la[2], lb[2];
    la[0] = *(const float4*)(Ap + ls);
    la[1] = *(const float4*)(Ap + ls + 4);
    lb[0] = *(const float4*)(Bp + ls);
    lb[1] = *(const float4*)(Bp + ls + 4);

    // store tile 0
    {
        uint4 sa0, sa1, sb0, sb1;
        sa0.x = f2tf(la[0].x); sa0.y = f2tf(la[0].y); sa0.z = f2tf(la[0].z); sa0.w = f2tf(la[0].w);
        sa1.x = f2tf(la[1].x); sa1.y = f2tf(la[1].y); sa1.z = f2tf(la[1].z); sa1.w = f2tf(la[1].w);
        sb0.x = f2tf(lb[0].x); sb0.y = f2tf(lb[0].y); sb0.z = f2tf(lb[0].z); sb0.w = f2tf(lb[0].w);
        sb1.x = f2tf(lb[1].x); sb1.y = f2tf(lb[1].y); sb1.z = f2tf(lb[1].z); sb1.w = f2tf(lb[1].w);
        *(uint4*)&As[0][lr * GSTR + ls]     = sa0;
        *(uint4*)&As[0][lr * GSTR + ls + 4] = sa1;
        *(uint4*)&Bs[0][lr * GSTR + ls]     = sb0;
        *(uint4*)&Bs[0][lr * GSTR + ls + 4] = sb1;
    }
    __syncthreads();

    int cur = 0;
    for (int k0 = 16; k0 <= K; k0 += 16) {
        const bool more = (k0 < K);
        if (more) {
            la[0] = *(const float4*)(Ap + k0 + ls);
            la[1] = *(const float4*)(Ap + k0 + ls + 4);
            lb[0] = *(const float4*)(Bp + k0 + ls);
            lb[1] = *(const float4*)(Bp + k0 + ls + 4);
        }

        const uint32_t* Ac = As[cur];
        const uint32_t* Bc = Bs[cur];
        #pragma unroll
        for (int kk = 0; kk < 16; kk += 8) {
            uint32_t af[4][4], bf[4][2];
            const int c = kk + tg;
            #pragma unroll
            for (int mi = 0; mi < 4; mi++) {
                int r = wm + mi * 16 + g;
                af[mi][0] = Ac[r * GSTR + c];
                af[mi][1] = Ac[(r + 8) * GSTR + c];
                af[mi][2] = Ac[r * GSTR + c + 4];
                af[mi][3] = Ac[(r + 8) * GSTR + c + 4];
            }
            #pragma unroll
            for (int ni = 0; ni < 4; ni++) {
                int r = wn + ni * 8 + g;
                bf[ni][0] = Bc[r * GSTR + c];
                bf[ni][1] = Bc[r * GSTR + c + 4];
            }
            #pragma unroll
            for (int mi = 0; mi < 4; mi++)
                #pragma unroll
                for (int ni = 0; ni < 4; ni++)
                    MMA_TF32(acc[mi][ni], af[mi], bf[ni]);
        }

        if (more) {
            int nxt = cur ^ 1;
            uint4 sa0, sa1, sb0, sb1;
            sa0.x = f2tf(la[0].x); sa0.y = f2tf(la[0].y); sa0.z = f2tf(la[0].z); sa0.w = f2tf(la[0].w);
            sa1.x = f2tf(la[1].x); sa1.y = f2tf(la[1].y); sa1.z = f2tf(la[1].z); sa1.w = f2tf(la[1].w);
            sb0.x = f2tf(lb[0].x); sb0.y = f2tf(lb[0].y); sb0.z = f2tf(lb[0].z); sb0.w = f2tf(lb[0].w);
            sb1.x = f2tf(lb[1].x); sb1.y = f2tf(lb[1].y); sb1.z = f2tf(lb[1].z); sb1.w = f2tf(lb[1].w);
            *(uint4*)&As[nxt][lr * GSTR + ls]     = sa0;
            *(uint4*)&As[nxt][lr * GSTR + ls + 4] = sa1;
            *(uint4*)&Bs[nxt][lr * GSTR + ls]     = sb0;
            *(uint4*)&Bs[nxt][lr * GSTR + ls + 4] = sb1;
        }
        __syncthreads();
        cur ^= 1;
    }

    // epilogue: route to C0 or C1
    float* Cp; const float* bp_; int ldc, cb;
    if (bn < CC) { Cp = C0; bp_ = bias0; ldc = CC;     cb = bn; }
    else         { Cp = C1; bp_ = bias1; ldc = 2 * CC; cb = bn - CC; }

    #pragma unroll
    for (int mi = 0; mi < 4; mi++) {
        int r0 = bm + wm + mi * 16 + g;
        #pragma unroll
        for (int ni = 0; ni < 4; ni++) {
            int c0 = cb + wn + ni * 8 + 2 * tg;
            float bx = bp_[c0], by = bp_[c0 + 1];
            *(float2*)&Cp[(size_t)r0 * ldc + c0] =
                make_float2(acc[mi][ni][0] + bx, acc[mi][ni][1] + by);
            *(float2*)&Cp[(size_t)(r0 + 8) * ldc + c0] =
                make_float2(acc[mi][ni][2] + bx, acc[mi][ni][3] + by);
        }
    }
}

// ================= Attention (tf32 mma) =================
#define QSTR 68
#define KSTR 68
#define VSTR 72
#define SSTR 1044
#define AT_Q_WORDS  (32 * QSTR)
#define AT_KV_WORDS (256 * VSTR)
#define AT_S_WORDS  (32 * SSTR)
#define AT_SMEM ((AT_Q_WORDS + AT_KV_WORDS + AT_S_WORDS) * 4)   // 216,064 B

__global__ __launch_bounds__(256) void mha_attn_tc(
    const float* __restrict__ gq, const float* __restrict__ gkv,
    float* __restrict__ go, float* __restrict__ gattn)
{
    extern __shared__ uint32_t sm_u[];
    uint32_t* Qs  = sm_u;
    uint32_t* KVs = sm_u + AT_Q_WORDS;
    float*    Sb  = (float*)(sm_u + AT_Q_WORDS + AT_KV_WORDS);

    const int t    = threadIdx.x;
    const int lane = t & 31;
    const int w    = t >> 5;
    const int g    = lane >> 2;
    const int tg   = lane & 3;
    const int nt   = blockIdx.x;
    const int h    = blockIdx.y;
    const int b    = blockIdx.z;
    const int n0   = nt * 32;

    #pragma unroll
    for (int r = 0; r < 2; r++) {
        int li = r * 256 + t;
        int n  = li >> 4;
        int dq = (li & 15) << 2;
        float4 v = *(const float4*)(gq + (size_t)(b * NN + n0 + n) * CC + h * DH + dq);
        uint4 u;
        u.x = f2tf(v.x); u.y = f2tf(v.y); u.z = f2tf(v.z); u.w = f2tf(v.w);
        *(uint4*)&Qs[n * QSTR + dq] = u;
    }
    __syncthreads();

    uint32_t qa[8][4];
    {
        int r = (w & 1) * 16 + g;
        #pragma unroll
        for (int kd = 0; kd < 8; kd++) {
            int c = kd * 8 + tg;
            qa[kd][0] = Qs[r * QSTR + c];
            qa[kd][1] = Qs[(r + 8) * QSTR + c];
            qa[kd][2] = Qs[r * QSTR + c + 4];
            qa[kd][3] = Qs[(r + 8) * QSTR + c + 4];
        }
    }

    const float* kbase = gkv + (size_t)(b * NN) * (2 * CC) + h * DH;
    const float* vbase = kbase + CC;

    for (int ch = 0; ch < 4; ch++) {
        const int m0 = ch * 256;
        __syncthreads();
        #pragma unroll
        for (int r = 0; r < 16; r++) {
            int li  = r * 256 + t;
            int row = li >> 4;
            int dq  = (li & 15) << 2;
            float4 v = *(const float4*)(kbase + (size_t)(m0 + row) * (2 * CC) + dq);
            uint4 u;
            u.x = f2tf(v.x); u.y = f2tf(v.y); u.z = f2tf(v.z); u.w = f2tf(v.w);
            *(uint4*)&KVs[row * KSTR + dq] = u;
        }
        __syncthreads();

        float acc[8][4];
        #pragma unroll
        for (int mt = 0; mt < 8; mt++)
            #pragma unroll
            for (int r = 0; r < 4; r++) acc[mt][r] = 0.0f;

        #pragma unroll
        for (int kd = 0; kd < 8; kd++) {
            uint32_t bf[8][2];
            #pragma unroll
            for (int mt = 0; mt < 8; mt++) {
                int r = (w >> 1) * 64 + mt * 8 + g;
                int c = kd * 8 + tg;
                bf[mt][0] = KVs[r * KSTR + c];
                bf[mt][1] = KVs[r * KSTR + c + 4];
            }
            #pragma unroll
            for (int mt = 0; mt < 8; mt++)
                MMA_TF32(acc[mt], qa[kd], bf[mt]);
        }

        int row = (w & 1) * 16 + g;
        #pragma unroll
        for (int mt = 0; mt < 8; mt++) {
            int col = m0 + (w >> 1) * 64 + mt * 8 + 2 * tg;
            Sb[row * SSTR + col]           = acc[mt][0] * 0.125f;
            Sb[row * SSTR + col + 1]       = acc[mt][1] * 0.125f;
            Sb[(row + 8) * SSTR + col]     = acc[mt][2] * 0.125f;
            Sb[(row + 8) * SSTR + col + 1] = acc[mt][3] * 0.125f;
        }
    }
    __syncthreads();

    {
        #pragma unroll
        for (int rr = 0; rr < 4; rr++) {
            float* row = Sb + (w * 4 + rr) * SSTR;
            float mx = -1e30f;
            for (int m = lane; m < 1024; m += 32) mx = fmaxf(mx, row[m]);
            #pragma unroll
            for (int o = 16; o; o >>= 1) mx = fmaxf(mx, __shfl_xor_sync(0xffffffffu, mx, o));
            float sum = 0.0f;
            for (int m = lane; m < 1024; m += 32) {
                float e = __expf(row[m] - mx);
                row[m] = e;
                sum += e;
            }
            #pragma unroll
            for (int o = 16; o; o >>= 1) sum += __shfl_xor_sync(0xffffffffu, sum, o);
            float inv = 1.0f / sum;
            for (int m = lane; m < 1024; m += 32) row[m] *= inv;
        }
    }
    __syncthreads();

    {
        float* dst = gattn + ((size_t)((b * HH + h) * NN + n0)) * NN;
        #pragma unroll
        for (int r = 0; r < 32; r++) {
            int li  = r * 256 + t;
            int row = li >> 8;
            int mq  = (li & 255) << 2;
            float4 v = *(const float4*)(Sb + row * SSTR + mq);
            *(float4*)(dst + (size_t)row * NN + mq) = v;
        }
    }

    float oacc[2][4];
    #pragma unroll
    for (int dt = 0; dt < 2; dt++)
        #pragma unroll
        for (int r = 0; r < 4; r++) oacc[dt][r] = 0.0f;

    for (int ch = 0; ch < 4; ch++) {
        const int m0 = ch * 256;
        __syncthreads();
        #pragma unroll
        for (int r = 0; r < 16; r++) {
            int li  = r * 256 + t;
            int row = li >> 4;
            int dq  = (li & 15) << 2;
            float4 v = *(const float4*)(vbase + (size_t)(m0 + row) * (2 * CC) + dq);
            uint4 u;
            u.x = f2tf(v.x); u.y = f2tf(v.y); u.z = f2tf(v.z); u.w = f2tf(v.w);
            *(uint4*)&KVs[row * VSTR + dq] = u;
        }
        __syncthreads();

        int arow = (w & 1) * 16 + g;
        #pragma unroll 8
        for (int ks = 0; ks < 32; ks++) {
            int mk = m0 + ks * 8;
            uint32_t af[4];
            af[0] = f2tf(Sb[arow * SSTR + mk + tg]);
            af[1] = f2tf(Sb[(arow + 8) * SSTR + mk + tg]);
            af[2] = f2tf(Sb[arow * SSTR + mk + tg + 4]);
            af[3] = f2tf(Sb[(arow + 8) * SSTR + mk + tg + 4]);
            uint32_t bf[2][2];
            #pragma unroll
            for (int dt = 0; dt < 2; dt++) {
                int vr = ks * 8 + tg;
                int vc = (w >> 1) * 16 + dt * 8 + g;
                bf[dt][0] = KVs[vr * VSTR + vc];
                bf[dt][1] = KVs[(vr + 4) * VSTR + vc];
            }
            MMA_TF32(oacc[0], af, bf[0]);
            MMA_TF32(oacc[1], af, bf[1]);
        }
    }

    {
        int row = (w & 1) * 16 + g;
        float* o0 = go + (size_t)(b * NN + n0 + row) * CC + h * DH + (w >> 1) * 16;
        int col = 2 * tg;
        #pragma unroll
        for (int dt = 0; dt < 2; dt++) {
            *(float2*)&o0[dt * 8 + col]          = make_float2(oacc[dt][0], oacc[dt][1]);
            *(float2*)&o0[8 * CC + dt * 8 + col] = make_float2(oacc[dt][2], oacc[dt][3]);
        }
    }
}

// ---------------- transpose attn: [b,h,n,m] -> [b,n,m,h] ----------------
__global__ __launch_bounds__(256) void mha_transpose_attn(
    const float* __restrict__ src, float* __restrict__ dst)
{
    __shared__ float tile[16][257];
    const int t  = threadIdx.x;
    const int mc = blockIdx.x;
    const int n  = blockIdx.y;
    const int b  = blockIdx.z;
    const int m0 = mc * 256;

    #pragma unroll
    for (int r = 0; r < 4; r++) {
        int li = r * 256 + t;
        int hh = li >> 6;
        int mq = (li & 63) << 2;
        float4 v = *(const float4*)(src + ((size_t)((b * HH + hh) * NN + n)) * NN + m0 + mq);
        tile[hh][mq]     = v.x;
        tile[hh][mq + 1] = v.y;
        tile[hh][mq + 2] = v.z;
        tile[hh][mq + 3] = v.w;
    }
    __syncthreads();

    float* dbase = dst + ((size_t)(b * NN + n) * NN + m0) * HH;
    #pragma unroll
    for (int r = 0; r < 4; r++) {
        int li = r * 256 + t;
        int m  = li >> 2;
        int hq = (li & 3) << 2;
        float4 v;
        v.x = tile[hq + 0][m];
        v.y = tile[hq + 1][m];
        v.z = tile[hq + 2][m];
        v.w = tile[hq + 3][m];
        *(float4*)(dbase + (size_t)m * HH + hq) = v;
    }
}

// ---------------- launch ----------------
extern "C" void kernel_launch(void* const* d_in, const int* in_sizes, int n_in,
                              void* d_out, int out_size)
{
    const float* x   = (const float*)d_in[0];
    const float* Wq  = (const float*)d_in[1];
    const float* bq  = (const float*)d_in[2];
    const float* Wkv = (const float*)d_in[3];
    const float* bkv = (const float*)d_in[4];
    const float* Wp  = (const float*)d_in[5];
    const float* bp  = (const float*)d_in[6];

    float* out      = (float*)d_out;
    float* attn_out = out + (size_t)OUT_ELEMS;

    float* q = nullptr; float* kv = nullptr; float* o = nullptr; float* attn = nullptr;
    cudaGetSymbolAddress((void**)&q,    g_mha_q);
    cudaGetSymbolAddress((void**)&kv,   g_mha_kv);
    cudaGetSymbolAddress((void**)&o,    g_mha_o);
    cudaGetSymbolAddress((void**)&attn, g_mha_attn);

    cudaFuncSetAttribute(mha_attn_tc,
                         cudaFuncAttributeMaxDynamicSharedMemorySize, AT_SMEM);

    // Fused: Q = x@Wq^T+bq  and  KV = x@Wkv^T+bkv  (cols 0..1023 -> q, 1024..3071 -> kv)
    mha_gemm8<<<dim3(3 * CC / 128, MROWS / 128), 256>>>(
        x, Wq, Wkv, bq, bkv, q, kv, CC);
    // attention
    mha_attn_tc<<<dim3(NN / 32, HH, BB), 256, AT_SMEM>>>(q, kv, o, attn);
    // out = O @ Wp^T + bp
    mha_gemm8<<<dim3(CC / 128, MROWS / 128), 256>>>(
        o, Wp, nullptr, bp, nullptr, out, nullptr, CC);
    // attn -> [b,n,m,h]
    if (out_size >= (int)(OUT_ELEMS + ATTN_ELEMS)) {
        mha_transpose_attn<<<dim3(NN / 256, NN, BB), 256>>>(attn, attn_out);
    }
}

// round 11
// speedup vs baseline: 2.4544x; 1.0643x over previous
#include <cuda_runtime.h>
#include <cuda_bf16.h>
#include <cstdint>
#include <cstddef>

// Problem constants
#define BB   2
#define NN   1024
#define CC   1024
#define HH   16
#define DH   64
#define MROWS (BB*NN)
#define OUT_ELEMS  (BB*NN*CC)                 // 2,097,152
#define ATTN_ELEMS (BB*NN*NN*HH)              // 33,554,432

// ---------------- scratch ----------------
__device__ float g_mha_q[MROWS * CC];
__device__ float g_mha_kv[MROWS * 2 * CC];
__device__ float g_mha_o[MROWS * CC];
__device__ float g_mha_attn[ATTN_ELEMS];      // [b,h,n,m]

// ---------------- tf32 helpers ----------------
__device__ __forceinline__ uint32_t f2tf(float x) {
    uint32_t r;
    asm("cvt.rna.tf32.f32 %0, %1;" : "=r"(r) : "f"(x));
    return r;
}

#define MMA_TF32(d, a, b) \
    asm volatile("mma.sync.aligned.m16n8k8.row.col.f32.tf32.tf32.f32 " \
        "{%0,%1,%2,%3}, {%4,%5,%6,%7}, {%8,%9}, {%0,%1,%2,%3};" \
        : "+f"((d)[0]), "+f"((d)[1]), "+f"((d)[2]), "+f"((d)[3]) \
        : "r"((a)[0]), "r"((a)[1]), "r"((a)[2]), "r"((a)[3]), \
          "r"((b)[0]), "r"((b)[1]))

// ================= GEMM: C = A @ B^T + bias, split-output =================
// 128x128 block, 256 threads (8 warps 2x4), warp 64x32, k-tile 16, dbl-buffered.
#define GSTR 20

__global__ __launch_bounds__(256) void mha_gemm8(
    const float* __restrict__ A,
    const float* __restrict__ B0, const float* __restrict__ B1,
    const float* __restrict__ bias0, const float* __restrict__ bias1,
    float* __restrict__ C0, float* __restrict__ C1, int K)
{
    __shared__ uint32_t As[2][128 * GSTR];
    __shared__ uint32_t Bs[2][128 * GSTR];

    const int t    = threadIdx.x;
    const int lane = t & 31;
    const int w    = t >> 5;
    const int bm   = blockIdx.y * 128;
    const int bn   = blockIdx.x * 128;
    const int wm   = (w >> 2) * 64;
    const int wn   = (w & 3) * 32;
    const int g    = lane >> 2;
    const int tg   = lane & 3;

    const int lr = t >> 1;
    const int ls = (t & 1) * 8;

    float acc[4][4][4];
    #pragma unroll
    for (int mi = 0; mi < 4; mi++)
        #pragma unroll
        for (int ni = 0; ni < 4; ni++)
            #pragma unroll
            for (int r = 0; r < 4; r++) acc[mi][ni][r] = 0.0f;

    const float* Ap = A + (size_t)(bm + lr) * K;
    const float* Bp;
    {
        int cn = bn + lr;
        Bp = (cn < CC) ? (B0 + (size_t)cn * K)
                       : (B1 + (size_t)(cn - CC) * K);
    }

    float4 la[2], lb[2];
    la[0] = *(const float4*)(Ap + ls);
    la[1] = *(const float4*)(Ap + ls + 4);
    lb[0] = *(const float4*)(Bp + ls);
    lb[1] = *(const float4*)(Bp + ls + 4);

    {
        uint4 sa0, sa1, sb0, sb1;
        sa0.x = f2tf(la[0].x); sa0.y = f2tf(la[0].y); sa0.z = f2tf(la[0].z); sa0.w = f2tf(la[0].w);
        sa1.x = f2tf(la[1].x); sa1.y = f2tf(la[1].y); sa1.z = f2tf(la[1].z); sa1.w = f2tf(la[1].w);
        sb0.x = f2tf(lb[0].x); sb0.y = f2tf(lb[0].y); sb0.z = f2tf(lb[0].z); sb0.w = f2tf(lb[0].w);
        sb1.x = f2tf(lb[1].x); sb1.y = f2tf(lb[1].y); sb1.z = f2tf(lb[1].z); sb1.w = f2tf(lb[1].w);
        *(uint4*)&As[0][lr * GSTR + ls]     = sa0;
        *(uint4*)&As[0][lr * GSTR + ls + 4] = sa1;
        *(uint4*)&Bs[0][lr * GSTR + ls]     = sb0;
        *(uint4*)&Bs[0][lr * GSTR + ls + 4] = sb1;
    }
    __syncthreads();

    int cur = 0;
    for (int k0 = 16; k0 <= K; k0 += 16) {
        const bool more = (k0 < K);
        if (more) {
            la[0] = *(const float4*)(Ap + k0 + ls);
            la[1] = *(const float4*)(Ap + k0 + ls + 4);
            lb[0] = *(const float4*)(Bp + k0 + ls);
            lb[1] = *(const float4*)(Bp + k0 + ls + 4);
        }

        const uint32_t* Ac = As[cur];
        const uint32_t* Bc = Bs[cur];
        #pragma unroll
        for (int kk = 0; kk < 16; kk += 8) {
            uint32_t af[4][4], bf[4][2];
            const int c = kk + tg;
            #pragma unroll
            for (int mi = 0; mi < 4; mi++) {
                int r = wm + mi * 16 + g;
                af[mi][0] = Ac[r * GSTR + c];
                af[mi][1] = Ac[(r + 8) * GSTR + c];
                af[mi][2] = Ac[r * GSTR + c + 4];
                af[mi][3] = Ac[(r + 8) * GSTR + c + 4];
            }
            #pragma unroll
            for (int ni = 0; ni < 4; ni++) {
                int r = wn + ni * 8 + g;
                bf[ni][0] = Bc[r * GSTR + c];
                bf[ni][1] = Bc[r * GSTR + c + 4];
            }
            #pragma unroll
            for (int mi = 0; mi < 4; mi++)
                #pragma unroll
                for (int ni = 0; ni < 4; ni++)
                    MMA_TF32(acc[mi][ni], af[mi], bf[ni]);
        }

        if (more) {
            int nxt = cur ^ 1;
            uint4 sa0, sa1, sb0, sb1;
            sa0.x = f2tf(la[0].x); sa0.y = f2tf(la[0].y); sa0.z = f2tf(la[0].z); sa0.w = f2tf(la[0].w);
            sa1.x = f2tf(la[1].x); sa1.y = f2tf(la[1].y); sa1.z = f2tf(la[1].z); sa1.w = f2tf(la[1].w);
            sb0.x = f2tf(lb[0].x); sb0.y = f2tf(lb[0].y); sb0.z = f2tf(lb[0].z); sb0.w = f2tf(lb[0].w);
            sb1.x = f2tf(lb[1].x); sb1.y = f2tf(lb[1].y); sb1.z = f2tf(lb[1].z); sb1.w = f2tf(lb[1].w);
            *(uint4*)&As[nxt][lr * GSTR + ls]     = sa0;
            *(uint4*)&As[nxt][lr * GSTR + ls + 4] = sa1;
            *(uint4*)&Bs[nxt][lr * GSTR + ls]     = sb0;
            *(uint4*)&Bs[nxt][lr * GSTR + ls + 4] = sb1;
        }
        __syncthreads();
        cur ^= 1;
    }

    float* Cp; const float* bp_; int ldc, cb;
    if (bn < CC) { Cp = C0; bp_ = bias0; ldc = CC;     cb = bn; }
    else         { Cp = C1; bp_ = bias1; ldc = 2 * CC; cb = bn - CC; }

    #pragma unroll
    for (int mi = 0; mi < 4; mi++) {
        int r0 = bm + wm + mi * 16 + g;
        #pragma unroll
        for (int ni = 0; ni < 4; ni++) {
            int c0 = cb + wn + ni * 8 + 2 * tg;
            float bx = bp_[c0], by = bp_[c0 + 1];
            *(float2*)&Cp[(size_t)r0 * ldc + c0] =
                make_float2(acc[mi][ni][0] + bx, acc[mi][ni][1] + by);
            *(float2*)&Cp[(size_t)(r0 + 8) * ldc + c0] =
                make_float2(acc[mi][ni][2] + bx, acc[mi][ni][3] + by);
        }
    }
}

// ================= Attention QK^T + softmax + attn scratch write =================
#define QSTR 68
#define KSTR 68
#define SSTR 1044
#define AT_Q_WORDS  (32 * QSTR)
#define AT_K_WORDS  (256 * KSTR)
#define AT_S_WORDS  (32 * SSTR)
#define AT_SMEM ((AT_Q_WORDS + AT_K_WORDS + AT_S_WORDS) * 4)   // 211,968 B

__global__ __launch_bounds__(256) void mha_attn_qk(
    const float* __restrict__ gq, const float* __restrict__ gkv,
    float* __restrict__ gattn)
{
    extern __shared__ uint32_t sm_u[];
    uint32_t* Qs = sm_u;
    uint32_t* Ks = sm_u + AT_Q_WORDS;
    float*    Sb = (float*)(sm_u + AT_Q_WORDS + AT_K_WORDS);

    const int t    = threadIdx.x;
    const int lane = t & 31;
    const int w    = t >> 5;
    const int g    = lane >> 2;
    const int tg   = lane & 3;
    const int nt   = blockIdx.x;
    const int h    = blockIdx.y;
    const int b    = blockIdx.z;
    const int n0   = nt * 32;

    #pragma unroll
    for (int r = 0; r < 2; r++) {
        int li = r * 256 + t;
        int n  = li >> 4;
        int dq = (li & 15) << 2;
        float4 v = *(const float4*)(gq + (size_t)(b * NN + n0 + n) * CC + h * DH + dq);
        uint4 u;
        u.x = f2tf(v.x); u.y = f2tf(v.y); u.z = f2tf(v.z); u.w = f2tf(v.w);
        *(uint4*)&Qs[n * QSTR + dq] = u;
    }
    __syncthreads();

    uint32_t qa[8][4];
    {
        int r = (w & 1) * 16 + g;
        #pragma unroll
        for (int kd = 0; kd < 8; kd++) {
            int c = kd * 8 + tg;
            qa[kd][0] = Qs[r * QSTR + c];
            qa[kd][1] = Qs[(r + 8) * QSTR + c];
            qa[kd][2] = Qs[r * QSTR + c + 4];
            qa[kd][3] = Qs[(r + 8) * QSTR + c + 4];
        }
    }

    const float* kbase = gkv + (size_t)(b * NN) * (2 * CC) + h * DH;

    for (int ch = 0; ch < 4; ch++) {
        const int m0 = ch * 256;
        __syncthreads();
        #pragma unroll
        for (int r = 0; r < 16; r++) {
            int li  = r * 256 + t;
            int row = li >> 4;
            int dq  = (li & 15) << 2;
            float4 v = *(const float4*)(kbase + (size_t)(m0 + row) * (2 * CC) + dq);
            uint4 u;
            u.x = f2tf(v.x); u.y = f2tf(v.y); u.z = f2tf(v.z); u.w = f2tf(v.w);
            *(uint4*)&Ks[row * KSTR + dq] = u;
        }
        __syncthreads();

        float acc[8][4];
        #pragma unroll
        for (int mt = 0; mt < 8; mt++)
            #pragma unroll
            for (int r = 0; r < 4; r++) acc[mt][r] = 0.0f;

        #pragma unroll
        for (int kd = 0; kd < 8; kd++) {
            uint32_t bf[8][2];
            #pragma unroll
            for (int mt = 0; mt < 8; mt++) {
                int r = (w >> 1) * 64 + mt * 8 + g;
                int c = kd * 8 + tg;
                bf[mt][0] = Ks[r * KSTR + c];
                bf[mt][1] = Ks[r * KSTR + c + 4];
            }
            #pragma unroll
            for (int mt = 0; mt < 8; mt++)
                MMA_TF32(acc[mt], qa[kd], bf[mt]);
        }

        int row = (w & 1) * 16 + g;
        #pragma unroll
        for (int mt = 0; mt < 8; mt++) {
            int col = m0 + (w >> 1) * 64 + mt * 8 + 2 * tg;
            Sb[row * SSTR + col]           = acc[mt][0] * 0.125f;
            Sb[row * SSTR + col + 1]       = acc[mt][1] * 0.125f;
            Sb[(row + 8) * SSTR + col]     = acc[mt][2] * 0.125f;
            Sb[(row + 8) * SSTR + col + 1] = acc[mt][3] * 0.125f;
        }
    }
    __syncthreads();

    // softmax over m (each warp: 4 rows)
    {
        #pragma unroll
        for (int rr = 0; rr < 4; rr++) {
            float* row = Sb + (w * 4 + rr) * SSTR;
            float mx = -1e30f;
            for (int m = lane; m < 1024; m += 32) mx = fmaxf(mx, row[m]);
            #pragma unroll
            for (int o = 16; o; o >>= 1) mx = fmaxf(mx, __shfl_xor_sync(0xffffffffu, mx, o));
            float sum = 0.0f;
            for (int m = lane; m < 1024; m += 32) {
                float e = __expf(row[m] - mx);
                row[m] = e;
                sum += e;
            }
            #pragma unroll
            for (int o = 16; o; o >>= 1) sum += __shfl_xor_sync(0xffffffffu, sum, o);
            float inv = 1.0f / sum;
            for (int m = lane; m < 1024; m += 32) row[m] *= inv;
        }
    }
    __syncthreads();

    // write attn scratch ([b,h,n,m], coalesced)
    {
        float* dst = gattn + ((size_t)((b * HH + h) * NN + n0)) * NN;
        #pragma unroll
        for (int r = 0; r < 32; r++) {
            int li  = r * 256 + t;
            int row = li >> 8;
            int mq  = (li & 255) << 2;
            float4 v = *(const float4*)(Sb + row * SSTR + mq);
            *(float4*)(dst + (size_t)row * NN + mq) = v;
        }
    }
}

// ================= PV batched GEMM: O[b,h,n,d] = P[b,h,n,:] @ V =================
// Block: (n-tile 128, h, b). 256 thr, 8 warps (4n x 2d), warp 32x32, k-chunk 32.
#define PSTR  36
#define PVSTR 68
#define PV_SMEM ((2 * 128 * PSTR + 2 * 32 * PVSTR) * 4)   // 54,272 B

__global__ __launch_bounds__(256) void mha_pv(
    const float* __restrict__ gattn, const float* __restrict__ gkv,
    float* __restrict__ go)
{
    extern __shared__ uint32_t ps[];
    uint32_t* Asm = ps;                      // [2][128*PSTR]
    uint32_t* Vsm = ps + 2 * 128 * PSTR;     // [2][32*PVSTR]

    const int t    = threadIdx.x;
    const int lane = t & 31;
    const int w    = t >> 5;
    const int g    = lane >> 2;
    const int tg   = lane & 3;
    const int nt   = blockIdx.x;     // 0..7
    const int h    = blockIdx.y;
    const int b    = blockIdx.z;
    const int wn   = (w >> 1) * 32;  // n offset in block
    const int wd   = (w & 1) * 32;   // d offset

    const float* Pbase = gattn + ((size_t)((b * HH + h) * NN + nt * 128)) * NN;
    const float* Vbase = gkv + (size_t)(b * NN) * (2 * CC) + CC + h * DH;

    float acc[2][4][4];
    #pragma unroll
    for (int mi = 0; mi < 2; mi++)
        #pragma unroll
        for (int ni = 0; ni < 4; ni++)
            #pragma unroll
            for (int r = 0; r < 4; r++) acc[mi][ni][r] = 0.0f;

    // A-load indices: 128 rows x 8 f4 (32 k floats)
    const int ar = t >> 1;             // via li = r*256+t: row = li>>3
    // V-load indices: 32 rows x 16 f4

    float4 pa[4], pv[2];
    #pragma unroll
    for (int r = 0; r < 4; r++) {
        int li  = r * 256 + t;
        int row = li >> 3;
        int fq  = (li & 7) << 2;
        pa[r] = *(const float4*)(Pbase + (size_t)row * NN + fq);
    }
    #pragma unroll
    for (int r = 0; r < 2; r++) {
        int li  = r * 256 + t;
        int row = li >> 4;
        int dq  = (li & 15) << 2;
        pv[r] = *(const float4*)(Vbase + (size_t)row * (2 * CC) + dq);
    }
    // store buffer 0
    #pragma unroll
    for (int r = 0; r < 4; r++) {
        int li  = r * 256 + t;
        int row = li >> 3;
        int fq  = (li & 7) << 2;
        uint4 u;
        u.x = f2tf(pa[r].x); u.y = f2tf(pa[r].y); u.z = f2tf(pa[r].z); u.w = f2tf(pa[r].w);
        *(uint4*)&Asm[row * PSTR + fq] = u;
    }
    #pragma unroll
    for (int r = 0; r < 2; r++) {
        int li  = r * 256 + t;
        int row = li >> 4;
        int dq  = (li & 15) << 2;
        uint4 u;
        u.x = f2tf(pv[r].x); u.y = f2tf(pv[r].y); u.z = f2tf(pv[r].z); u.w = f2tf(pv[r].w);
        *(uint4*)&Vsm[row * PVSTR + dq] = u;
    }
    __syncthreads();

    int cur = 0;
    for (int k0 = 32; k0 <= 1024; k0 += 32) {
        const bool more = (k0 < 1024);
        if (more) {
            #pragma unroll
            for (int r = 0; r < 4; r++) {
                int li  = r * 256 + t;
                int row = li >> 3;
                int fq  = (li & 7) << 2;
                pa[r] = *(const float4*)(Pbase + (size_t)row * NN + k0 + fq);
            }
            #pragma unroll
            for (int r = 0; r < 2; r++) {
                int li  = r * 256 + t;
                int row = li >> 4;
                int dq  = (li & 15) << 2;
                pv[r] = *(const float4*)(Vbase + (size_t)(k0 + row) * (2 * CC) + dq);
            }
        }

        const uint32_t* Ac = Asm + cur * (128 * PSTR);
        const uint32_t* Vc = Vsm + cur * (32 * PVSTR);
        #pragma unroll
        for (int kk = 0; kk < 32; kk += 8) {
            uint32_t af[2][4], bf[4][2];
            const int c = kk + tg;
            #pragma unroll
            for (int mi = 0; mi < 2; mi++) {
                int r = wn + mi * 16 + g;
                af[mi][0] = Ac[r * PSTR + c];
                af[mi][1] = Ac[(r + 8) * PSTR + c];
                af[mi][2] = Ac[r * PSTR + c + 4];
                af[mi][3] = Ac[(r + 8) * PSTR + c + 4];
            }
            #pragma unroll
            for (int ni = 0; ni < 4; ni++) {
                int vc = wd + ni * 8 + g;
                bf[ni][0] = Vc[c * PVSTR + vc];
                bf[ni][1] = Vc[(c + 4) * PVSTR + vc];
            }
            #pragma unroll
            for (int mi = 0; mi < 2; mi++)
                #pragma unroll
                for (int ni = 0; ni < 4; ni++)
                    MMA_TF32(acc[mi][ni], af[mi], bf[ni]);
        }

        if (more) {
            uint32_t* An = Asm + (cur ^ 1) * (128 * PSTR);
            uint32_t* Vn = Vsm + (cur ^ 1) * (32 * PVSTR);
            #pragma unroll
            for (int r = 0; r < 4; r++) {
                int li  = r * 256 + t;
                int row = li >> 3;
                int fq  = (li & 7) << 2;
                uint4 u;
                u.x = f2tf(pa[r].x); u.y = f2tf(pa[r].y); u.z = f2tf(pa[r].z); u.w = f2tf(pa[r].w);
                *(uint4*)&An[row * PSTR + fq] = u;
            }
            #pragma unroll
            for (int r = 0; r < 2; r++) {
                int li  = r * 256 + t;
                int row = li >> 4;
                int dq  = (li & 15) << 2;
                uint4 u;
                u.x = f2tf(pv[r].x); u.y = f2tf(pv[r].y); u.z = f2tf(pv[r].z); u.w = f2tf(pv[r].w);
                *(uint4*)&Vn[row * PVSTR + dq] = u;
            }
        }
        __syncthreads();
        cur ^= 1;
    }

    #pragma unroll
    for (int mi = 0; mi < 2; mi++) {
        int r0 = b * NN + nt * 128 + wn + mi * 16 + g;
        #pragma unroll
        for (int ni = 0; ni < 4; ni++) {
            int c0 = h * DH + wd + ni * 8 + 2 * tg;
            *(float2*)&go[(size_t)r0 * CC + c0] =
                make_float2(acc[mi][ni][0], acc[mi][ni][1]);
            *(float2*)&go[(size_t)(r0 + 8) * CC + c0] =
                make_float2(acc[mi][ni][2], acc[mi][ni][3]);
        }
    }
}

// ---------------- transpose attn: [b,h,n,m] -> [b,n,m,h] ----------------
__global__ __launch_bounds__(256) void mha_transpose_attn(
    const float* __restrict__ src, float* __restrict__ dst)
{
    __shared__ float tile[16][257];
    const int t  = threadIdx.x;
    const int mc = blockIdx.x;
    const int n  = blockIdx.y;
    const int b  = blockIdx.z;
    const int m0 = mc * 256;

    #pragma unroll
    for (int r = 0; r < 4; r++) {
        int li = r * 256 + t;
        int hh = li >> 6;
        int mq = (li & 63) << 2;
        float4 v = *(const float4*)(src + ((size_t)((b * HH + hh) * NN + n)) * NN + m0 + mq);
        tile[hh][mq]     = v.x;
        tile[hh][mq + 1] = v.y;
        tile[hh][mq + 2] = v.z;
        tile[hh][mq + 3] = v.w;
    }
    __syncthreads();

    float* dbase = dst + ((size_t)(b * NN + n) * NN + m0) * HH;
    #pragma unroll
    for (int r = 0; r < 4; r++) {
        int li = r * 256 + t;
        int m  = li >> 2;
        int hq = (li & 3) << 2;
        float4 v;
        v.x = tile[hq + 0][m];
        v.y = tile[hq + 1][m];
        v.z = tile[hq + 2][m];
        v.w = tile[hq + 3][m];
        *(float4*)(dbase + (size_t)m * HH + hq) = v;
    }
}

// ---------------- launch ----------------
extern "C" void kernel_launch(void* const* d_in, const int* in_sizes, int n_in,
                              void* d_out, int out_size)
{
    const float* x   = (const float*)d_in[0];
    const float* Wq  = (const float*)d_in[1];
    const float* bq  = (const float*)d_in[2];
    const float* Wkv = (const float*)d_in[3];
    const float* bkv = (const float*)d_in[4];
    const float* Wp  = (const float*)d_in[5];
    const float* bp  = (const float*)d_in[6];

    float* out      = (float*)d_out;
    float* attn_out = out + (size_t)OUT_ELEMS;

    float* q = nullptr; float* kv = nullptr; float* o = nullptr; float* attn = nullptr;
    cudaGetSymbolAddress((void**)&q,    g_mha_q);
    cudaGetSymbolAddress((void**)&kv,   g_mha_kv);
    cudaGetSymbolAddress((void**)&o,    g_mha_o);
    cudaGetSymbolAddress((void**)&attn, g_mha_attn);

    cudaFuncSetAttribute(mha_attn_qk,
                         cudaFuncAttributeMaxDynamicSharedMemorySize, AT_SMEM);
    cudaFuncSetAttribute(mha_pv,
                         cudaFuncAttributeMaxDynamicSharedMemorySize, PV_SMEM);

    // Fused: Q = x@Wq^T+bq and KV = x@Wkv^T+bkv
    mha_gemm8<<<dim3(3 * CC / 128, MROWS / 128), 256>>>(
        x, Wq, Wkv, bq, bkv, q, kv, CC);
    // QK^T + softmax -> attn scratch [b,h,n,m]
    mha_attn_qk<<<dim3(NN / 32, HH, BB), 256, AT_SMEM>>>(q, kv, attn);
    // O = P @ V (batched GEMM from scratch)
    mha_pv<<<dim3(NN / 128, HH, BB), 256, PV_SMEM>>>(attn, kv, o);
    // out = O @ Wp^T + bp
    mha_gemm8<<<dim3(CC / 128, MROWS / 128), 256>>>(
        o, Wp, nullptr, bp, nullptr, out, nullptr, CC);
    // attn -> [b,n,m,h]
    if (out_size >= (int)(OUT_ELEMS + ATTN_ELEMS)) {
        mha_transpose_attn<<<dim3(NN / 256, NN, BB), 256>>>(attn, attn_out);
    }
}

// round 12
// speedup vs baseline: 2.4681x; 1.0056x over previous
#include <cuda_runtime.h>
#include <cuda_bf16.h>
#include <cstdint>
#include <cstddef>

// Problem constants
#define BB   2
#define NN   1024
#define CC   1024
#define HH   16
#define DH   64
#define MROWS (BB*NN)
#define OUT_ELEMS  (BB*NN*CC)                 // 2,097,152
#define ATTN_ELEMS (BB*NN*NN*HH)              // 33,554,432

// ---------------- scratch ----------------
__device__ float g_mha_q[MROWS * CC];
__device__ float g_mha_kv[MROWS * 2 * CC];
__device__ float g_mha_o[MROWS * CC];
__device__ float g_mha_attn[ATTN_ELEMS];      // [b,h,n,m]

// ---------------- tf32 helpers ----------------
__device__ __forceinline__ uint32_t f2tf(float x) {
    uint32_t r;
    asm("cvt.rna.tf32.f32 %0, %1;" : "=r"(r) : "f"(x));
    return r;
}

#define MMA_TF32(d, a, b) \
    asm volatile("mma.sync.aligned.m16n8k8.row.col.f32.tf32.tf32.f32 " \
        "{%0,%1,%2,%3}, {%4,%5,%6,%7}, {%8,%9}, {%0,%1,%2,%3};" \
        : "+f"((d)[0]), "+f"((d)[1]), "+f"((d)[2]), "+f"((d)[3]) \
        : "r"((a)[0]), "r"((a)[1]), "r"((a)[2]), "r"((a)[3]), \
          "r"((b)[0]), "r"((b)[1]))

// ================= GEMM: C = A @ B^T + bias, split-output =================
// 128x128 block, 512 threads (16 warps, 4m x 4n), warp tile 32x32, k-tile 16.
// Double-buffered smem, one __syncthreads per k-iter.
#define GSTR 20

__global__ __launch_bounds__(512) void mha_gemm8(
    const float* __restrict__ A,
    const float* __restrict__ B0, const float* __restrict__ B1,
    const float* __restrict__ bias0, const float* __restrict__ bias1,
    float* __restrict__ C0, float* __restrict__ C1, int K)
{
    __shared__ uint32_t As[2][128 * GSTR];
    __shared__ uint32_t Bs[2][128 * GSTR];

    const int t    = threadIdx.x;
    const int lane = t & 31;
    const int w    = t >> 5;         // 0..15
    const int bm   = blockIdx.y * 128;
    const int bn   = blockIdx.x * 128;
    const int wm   = (w >> 2) * 32;  // 0,32,64,96
    const int wn   = (w & 3) * 32;   // 0,32,64,96
    const int g    = lane >> 2;      // 0..7
    const int tg   = lane & 3;       // 0..3

    const int lr = t >> 2;           // 0..127 (tile row for loads)
    const int ls = (t & 3) * 4;      // k segment 0,4,8,12

    float acc[2][4][4];
    #pragma unroll
    for (int mi = 0; mi < 2; mi++)
        #pragma unroll
        for (int ni = 0; ni < 4; ni++)
            #pragma unroll
            for (int r = 0; r < 4; r++) acc[mi][ni][r] = 0.0f;

    const float* Ap = A + (size_t)(bm + lr) * K;
    const float* Bp;
    {
        int cn = bn + lr;
        Bp = (cn < CC) ? (B0 + (size_t)cn * K)
                       : (B1 + (size_t)(cn - CC) * K);
    }

    float4 la = *(const float4*)(Ap + ls);
    float4 lb = *(const float4*)(Bp + ls);

    {
        uint4 sa, sb;
        sa.x = f2tf(la.x); sa.y = f2tf(la.y); sa.z = f2tf(la.z); sa.w = f2tf(la.w);
        sb.x = f2tf(lb.x); sb.y = f2tf(lb.y); sb.z = f2tf(lb.z); sb.w = f2tf(lb.w);
        *(uint4*)&As[0][lr * GSTR + ls] = sa;
        *(uint4*)&Bs[0][lr * GSTR + ls] = sb;
    }
    __syncthreads();

    int cur = 0;
    for (int k0 = 16; k0 <= K; k0 += 16) {
        const bool more = (k0 < K);
        if (more) {
            la = *(const float4*)(Ap + k0 + ls);
            lb = *(const float4*)(Bp + k0 + ls);
        }

        const uint32_t* Ac = As[cur];
        const uint32_t* Bc = Bs[cur];
        #pragma unroll
        for (int kk = 0; kk < 16; kk += 8) {
            uint32_t af[2][4], bf[4][2];
            const int c = kk + tg;
            #pragma unroll
            for (int mi = 0; mi < 2; mi++) {
                int r = wm + mi * 16 + g;
                af[mi][0] = Ac[r * GSTR + c];
                af[mi][1] = Ac[(r + 8) * GSTR + c];
                af[mi][2] = Ac[r * GSTR + c + 4];
                af[mi][3] = Ac[(r + 8) * GSTR + c + 4];
            }
            #pragma unroll
            for (int ni = 0; ni < 4; ni++) {
                int r = wn + ni * 8 + g;
                bf[ni][0] = Bc[r * GSTR + c];
                bf[ni][1] = Bc[r * GSTR + c + 4];
            }
            #pragma unroll
            for (int mi = 0; mi < 2; mi++)
                #pragma unroll
                for (int ni = 0; ni < 4; ni++)
                    MMA_TF32(acc[mi][ni], af[mi], bf[ni]);
        }

        if (more) {
            int nxt = cur ^ 1;
            uint4 sa, sb;
            sa.x = f2tf(la.x); sa.y = f2tf(la.y); sa.z = f2tf(la.z); sa.w = f2tf(la.w);
            sb.x = f2tf(lb.x); sb.y = f2tf(lb.y); sb.z = f2tf(lb.z); sb.w = f2tf(lb.w);
            *(uint4*)&As[nxt][lr * GSTR + ls] = sa;
            *(uint4*)&Bs[nxt][lr * GSTR + ls] = sb;
        }
        __syncthreads();
        cur ^= 1;
    }

    float* Cp; const float* bp_; int ldc, cb;
    if (bn < CC) { Cp = C0; bp_ = bias0; ldc = CC;     cb = bn; }
    else         { Cp = C1; bp_ = bias1; ldc = 2 * CC; cb = bn - CC; }

    #pragma unroll
    for (int mi = 0; mi < 2; mi++) {
        int r0 = bm + wm + mi * 16 + g;
        #pragma unroll
        for (int ni = 0; ni < 4; ni++) {
            int c0 = cb + wn + ni * 8 + 2 * tg;
            float bx = bp_[c0], by = bp_[c0 + 1];
            *(float2*)&Cp[(size_t)r0 * ldc + c0] =
                make_float2(acc[mi][ni][0] + bx, acc[mi][ni][1] + by);
            *(float2*)&Cp[(size_t)(r0 + 8) * ldc + c0] =
                make_float2(acc[mi][ni][2] + bx, acc[mi][ni][3] + by);
        }
    }
}

// ================= Attention QK^T + softmax + attn scratch write =================
// 512 threads (16 warps). Warp: n-half = w&1 (16 rows), m-slice = (w>>1)*32.
#define QSTR 68
#define KSTR 68
#define SSTR 1044
#define AT_Q_WORDS  (32 * QSTR)
#define AT_K_WORDS  (256 * KSTR)
#define AT_S_WORDS  (32 * SSTR)
#define AT_SMEM ((AT_Q_WORDS + AT_K_WORDS + AT_S_WORDS) * 4)   // 211,968 B

__global__ __launch_bounds__(512) void mha_attn_qk(
    const float* __restrict__ gq, const float* __restrict__ gkv,
    float* __restrict__ gattn)
{
    extern __shared__ uint32_t sm_u[];
    uint32_t* Qs = sm_u;
    uint32_t* Ks = sm_u + AT_Q_WORDS;
    float*    Sb = (float*)(sm_u + AT_Q_WORDS + AT_K_WORDS);

    const int t    = threadIdx.x;
    const int lane = t & 31;
    const int w    = t >> 5;         // 0..15
    const int g    = lane >> 2;
    const int tg   = lane & 3;
    const int nt   = blockIdx.x;
    const int h    = blockIdx.y;
    const int b    = blockIdx.z;
    const int n0   = nt * 32;

    // ---- load Q tile (32 x 64): 512 float4 slots, one per thread ----
    {
        int n  = t >> 4;
        int dq = (t & 15) << 2;
        float4 v = *(const float4*)(gq + (size_t)(b * NN + n0 + n) * CC + h * DH + dq);
        uint4 u;
        u.x = f2tf(v.x); u.y = f2tf(v.y); u.z = f2tf(v.z); u.w = f2tf(v.w);
        *(uint4*)&Qs[n * QSTR + dq] = u;
    }
    __syncthreads();

    // ---- Q fragments register-resident (n-half = w&1) ----
    uint32_t qa[8][4];
    {
        int r = (w & 1) * 16 + g;
        #pragma unroll
        for (int kd = 0; kd < 8; kd++) {
            int c = kd * 8 + tg;
            qa[kd][0] = Qs[r * QSTR + c];
            qa[kd][1] = Qs[(r + 8) * QSTR + c];
            qa[kd][2] = Qs[r * QSTR + c + 4];
            qa[kd][3] = Qs[(r + 8) * QSTR + c + 4];
        }
    }

    const float* kbase = gkv + (size_t)(b * NN) * (2 * CC) + h * DH;

    for (int ch = 0; ch < 4; ch++) {
        const int m0 = ch * 256;
        __syncthreads();
        #pragma unroll
        for (int r = 0; r < 8; r++) {
            int li  = r * 512 + t;               // 4096 f4 slots
            int row = li >> 4;
            int dq  = (li & 15) << 2;
            float4 v = *(const float4*)(kbase + (size_t)(m0 + row) * (2 * CC) + dq);
            uint4 u;
            u.x = f2tf(v.x); u.y = f2tf(v.y); u.z = f2tf(v.z); u.w = f2tf(v.w);
            *(uint4*)&Ks[row * KSTR + dq] = u;
        }
        __syncthreads();

        float acc[4][4];
        #pragma unroll
        for (int mt = 0; mt < 4; mt++)
            #pragma unroll
            for (int r = 0; r < 4; r++) acc[mt][r] = 0.0f;

        const int ms = (w >> 1) * 32;            // warp's m-slice in chunk
        #pragma unroll
        for (int kd = 0; kd < 8; kd++) {
            uint32_t bf[4][2];
            #pragma unroll
            for (int mt = 0; mt < 4; mt++) {
                int r = ms + mt * 8 + g;
                int c = kd * 8 + tg;
                bf[mt][0] = Ks[r * KSTR + c];
                bf[mt][1] = Ks[r * KSTR + c + 4];
            }
            #pragma unroll
            for (int mt = 0; mt < 4; mt++)
                MMA_TF32(acc[mt], qa[kd], bf[mt]);
        }

        int row = (w & 1) * 16 + g;
        #pragma unroll
        for (int mt = 0; mt < 4; mt++) {
            int col = m0 + ms + mt * 8 + 2 * tg;
            Sb[row * SSTR + col]           = acc[mt][0] * 0.125f;
            Sb[row * SSTR + col + 1]       = acc[mt][1] * 0.125f;
            Sb[(row + 8) * SSTR + col]     = acc[mt][2] * 0.125f;
            Sb[(row + 8) * SSTR + col + 1] = acc[mt][3] * 0.125f;
        }
    }
    __syncthreads();

    // ---- softmax over m (each warp: 2 rows) ----
    {
        #pragma unroll
        for (int rr = 0; rr < 2; rr++) {
            float* row = Sb + (w * 2 + rr) * SSTR;
            float mx = -1e30f;
            for (int m = lane; m < 1024; m += 32) mx = fmaxf(mx, row[m]);
            #pragma unroll
            for (int o = 16; o; o >>= 1) mx = fmaxf(mx, __shfl_xor_sync(0xffffffffu, mx, o));
            float sum = 0.0f;
            for (int m = lane; m < 1024; m += 32) {
                float e = __expf(row[m] - mx);
                row[m] = e;
                sum += e;
            }
            #pragma unroll
            for (int o = 16; o; o >>= 1) sum += __shfl_xor_sync(0xffffffffu, sum, o);
            float inv = 1.0f / sum;
            for (int m = lane; m < 1024; m += 32) row[m] *= inv;
        }
    }
    __syncthreads();

    // ---- write attn scratch ([b,h,n,m], coalesced) ----
    {
        float* dst = gattn + ((size_t)((b * HH + h) * NN + n0)) * NN;
        #pragma unroll
        for (int r = 0; r < 16; r++) {
            int li  = r * 512 + t;               // 8192 f4 slots
            int row = li >> 8;
            int mq  = (li & 255) << 2;
            float4 v = *(const float4*)(Sb + row * SSTR + mq);
            *(float4*)(dst + (size_t)row * NN + mq) = v;
        }
    }
}

// ================= PV batched GEMM: O = P @ V =================
// Block: (n-tile 128, h, b). 512 thr, 16 warps (4n x 4d), warp 32x16, k-chunk 32.
#define PSTR  36
#define PVSTR 68
#define PV_SMEM ((2 * 128 * PSTR + 2 * 32 * PVSTR) * 4)   // 54,272 B

__global__ __launch_bounds__(512) void mha_pv(
    const float* __restrict__ gattn, const float* __restrict__ gkv,
    float* __restrict__ go)
{
    extern __shared__ uint32_t ps[];
    uint32_t* Asm = ps;                      // [2][128*PSTR]
    uint32_t* Vsm = ps + 2 * 128 * PSTR;     // [2][32*PVSTR]

    const int t    = threadIdx.x;
    const int lane = t & 31;
    const int w    = t >> 5;         // 0..15
    const int g    = lane >> 2;
    const int tg   = lane & 3;
    const int nt   = blockIdx.x;
    const int h    = blockIdx.y;
    const int b    = blockIdx.z;
    const int wn   = (w >> 2) * 32;  // n offset
    const int wd   = (w & 3) * 16;   // d offset

    const float* Pbase = gattn + ((size_t)((b * HH + h) * NN + nt * 128)) * NN;
    const float* Vbase = gkv + (size_t)(b * NN) * (2 * CC) + CC + h * DH;

    float acc[2][2][4];
    #pragma unroll
    for (int mi = 0; mi < 2; mi++)
        #pragma unroll
        for (int ni = 0; ni < 2; ni++)
            #pragma unroll
            for (int r = 0; r < 4; r++) acc[mi][ni][r] = 0.0f;

    float4 pa[2], pv;
    #pragma unroll
    for (int r = 0; r < 2; r++) {
        int li  = r * 512 + t;                // 1024 f4 slots: 128 rows x 8 f4
        int row = li >> 3;
        int fq  = (li & 7) << 2;
        pa[r] = *(const float4*)(Pbase + (size_t)row * NN + fq);
    }
    {
        int row = t >> 4;                     // 512 f4 slots: 32 rows x 16 f4
        int dq  = (t & 15) << 2;
        pv = *(const float4*)(Vbase + (size_t)row * (2 * CC) + dq);
    }
    #pragma unroll
    for (int r = 0; r < 2; r++) {
        int li  = r * 512 + t;
        int row = li >> 3;
        int fq  = (li & 7) << 2;
        uint4 u;
        u.x = f2tf(pa[r].x); u.y = f2tf(pa[r].y); u.z = f2tf(pa[r].z); u.w = f2tf(pa[r].w);
        *(uint4*)&Asm[row * PSTR + fq] = u;
    }
    {
        int row = t >> 4;
        int dq  = (t & 15) << 2;
        uint4 u;
        u.x = f2tf(pv.x); u.y = f2tf(pv.y); u.z = f2tf(pv.z); u.w = f2tf(pv.w);
        *(uint4*)&Vsm[row * PVSTR + dq] = u;
    }
    __syncthreads();

    int cur = 0;
    for (int k0 = 32; k0 <= 1024; k0 += 32) {
        const bool more = (k0 < 1024);
        if (more) {
            #pragma unroll
            for (int r = 0; r < 2; r++) {
                int li  = r * 512 + t;
                int row = li >> 3;
                int fq  = (li & 7) << 2;
                pa[r] = *(const float4*)(Pbase + (size_t)row * NN + k0 + fq);
            }
            {
                int row = t >> 4;
                int dq  = (t & 15) << 2;
                pv = *(const float4*)(Vbase + (size_t)(k0 + row) * (2 * CC) + dq);
            }
        }

        const uint32_t* Ac = Asm + cur * (128 * PSTR);
        const uint32_t* Vc = Vsm + cur * (32 * PVSTR);
        #pragma unroll
        for (int kk = 0; kk < 32; kk += 8) {
            uint32_t af[2][4], bf[2][2];
            const int c = kk + tg;
            #pragma unroll
            for (int mi = 0; mi < 2; mi++) {
                int r = wn + mi * 16 + g;
                af[mi][0] = Ac[r * PSTR + c];
                af[mi][1] = Ac[(r + 8) * PSTR + c];
                af[mi][2] = Ac[r * PSTR + c + 4];
                af[mi][3] = Ac[(r + 8) * PSTR + c + 4];
            }
            #pragma unroll
            for (int ni = 0; ni < 2; ni++) {
                int vc = wd + ni * 8 + g;
                bf[ni][0] = Vc[c * PVSTR + vc];
                bf[ni][1] = Vc[(c + 4) * PVSTR + vc];
            }
            #pragma unroll
            for (int mi = 0; mi < 2; mi++)
                #pragma unroll
                for (int ni = 0; ni < 2; ni++)
                    MMA_TF32(acc[mi][ni], af[mi], bf[ni]);
        }

        if (more) {
            uint32_t* An = Asm + (cur ^ 1) * (128 * PSTR);
            uint32_t* Vn = Vsm + (cur ^ 1) * (32 * PVSTR);
            #pragma unroll
            for (int r = 0; r < 2; r++) {
                int li  = r * 512 + t;
                int row = li >> 3;
                int fq  = (li & 7) << 2;
                uint4 u;
                u.x = f2tf(pa[r].x); u.y = f2tf(pa[r].y); u.z = f2tf(pa[r].z); u.w = f2tf(pa[r].w);
                *(uint4*)&An[row * PSTR + fq] = u;
            }
            {
                int row = t >> 4;
                int dq  = (t & 15) << 2;
                uint4 u;
                u.x = f2tf(pv.x); u.y = f2tf(pv.y); u.z = f2tf(pv.z); u.w = f2tf(pv.w);
                *(uint4*)&Vn[row * PVSTR + dq] = u;
            }
        }
        __syncthreads();
        cur ^= 1;
    }

    #pragma unroll
    for (int mi = 0; mi < 2; mi++) {
        int r0 = b * NN + nt * 128 + wn + mi * 16 + g;
        #pragma unroll
        for (int ni = 0; ni < 2; ni++) {
            int c0 = h * DH + wd + ni * 8 + 2 * tg;
            *(float2*)&go[(size_t)r0 * CC + c0] =
                make_float2(acc[mi][ni][0], acc[mi][ni][1]);
            *(float2*)&go[(size_t)(r0 + 8) * CC + c0] =
                make_float2(acc[mi][ni][2], acc[mi][ni][3]);
        }
    }
}

// ---------------- transpose attn: [b,h,n,m] -> [b,n,m,h] ----------------
__global__ __launch_bounds__(256) void mha_transpose_attn(
    const float* __restrict__ src, float* __restrict__ dst)
{
    __shared__ float tile[16][257];
    const int t  = threadIdx.x;
    const int mc = blockIdx.x;
    const int n  = blockIdx.y;
    const int b  = blockIdx.z;
    const int m0 = mc * 256;

    #pragma unroll
    for (int r = 0; r < 4; r++) {
        int li = r * 256 + t;
        int hh = li >> 6;
        int mq = (li & 63) << 2;
        float4 v = *(const float4*)(src + ((size_t)((b * HH + hh) * NN + n)) * NN + m0 + mq);
        tile[hh][mq]     = v.x;
        tile[hh][mq + 1] = v.y;
        tile[hh][mq + 2] = v.z;
        tile[hh][mq + 3] = v.w;
    }
    __syncthreads();

    float* dbase = dst + ((size_t)(b * NN + n) * NN + m0) * HH;
    #pragma unroll
    for (int r = 0; r < 4; r++) {
        int li = r * 256 + t;
        int m  = li >> 2;
        int hq = (li & 3) << 2;
        float4 v;
        v.x = tile[hq + 0][m];
        v.y = tile[hq + 1][m];
        v.z = tile[hq + 2][m];
        v.w = tile[hq + 3][m];
        *(float4*)(dbase + (size_t)m * HH + hq) = v;
    }
}

// ---------------- launch ----------------
extern "C" void kernel_launch(void* const* d_in, const int* in_sizes, int n_in,
                              void* d_out, int out_size)
{
    const float* x   = (const float*)d_in[0];
    const float* Wq  = (const float*)d_in[1];
    const float* bq  = (const float*)d_in[2];
    const float* Wkv = (const float*)d_in[3];
    const float* bkv = (const float*)d_in[4];
    const float* Wp  = (const float*)d_in[5];
    const float* bp  = (const float*)d_in[6];

    float* out      = (float*)d_out;
    float* attn_out = out + (size_t)OUT_ELEMS;

    float* q = nullptr; float* kv = nullptr; float* o = nullptr; float* attn = nullptr;
    cudaGetSymbolAddress((void**)&q,    g_mha_q);
    cudaGetSymbolAddress((void**)&kv,   g_mha_kv);
    cudaGetSymbolAddress((void**)&o,    g_mha_o);
    cudaGetSymbolAddress((void**)&attn, g_mha_attn);

    cudaFuncSetAttribute(mha_attn_qk,
                         cudaFuncAttributeMaxDynamicSharedMemorySize, AT_SMEM);
    cudaFuncSetAttribute(mha_pv,
                         cudaFuncAttributeMaxDynamicSharedMemorySize, PV_SMEM);

    // Fused: Q = x@Wq^T+bq and KV = x@Wkv^T+bkv
    mha_gemm8<<<dim3(3 * CC / 128, MROWS / 128), 512>>>(
        x, Wq, Wkv, bq, bkv, q, kv, CC);
    // QK^T + softmax -> attn scratch [b,h,n,m]
    mha_attn_qk<<<dim3(NN / 32, HH, BB), 512, AT_SMEM>>>(q, kv, attn);
    // O = P @ V
    mha_pv<<<dim3(NN / 128, HH, BB), 512, PV_SMEM>>>(attn, kv, o);
    // out = O @ Wp^T + bp
    mha_gemm8<<<dim3(CC / 128, MROWS / 128), 512>>>(
        o, Wp, nullptr, bp, nullptr, out, nullptr, CC);
    // attn -> [b,n,m,h]
    if (out_size >= (int)(OUT_ELEMS + ATTN_ELEMS)) {
        mha_transpose_attn<<<dim3(NN / 256, NN, BB), 256>>>(attn, attn_out);
    }
}